// round 9
// baseline (speedup 1.0000x reference)
#include <cuda_runtime.h>
#include <math.h>

#define TT 1500
#define BB 16
#define FF 440
#define HH 512
#define MM (TT*BB)      // 24000
#define NC 128          // persistent recurrence CTAs (single wave)

typedef unsigned long long ull;

// ---------------- device scratch (no allocations allowed) -------------------
__device__ float g_wh0[MM*HH];
__device__ float g_wz0[MM*HH];
__device__ float g_wh1[MM*HH];
__device__ float g_wz1[MM*HH];
__device__ float g_h1 [MM*HH];
__device__ float g_hbuf[2*BB*HH];
__device__ unsigned g_slots[NC];   // zero-init; monotonic arrivals per CTA
__device__ unsigned g_gen;         // zero-init; completed barrier generations

// ---------------- helpers ----------------------------------------------------
__device__ __forceinline__ unsigned ld_acq(const unsigned* p) {
    unsigned v;
    asm volatile("ld.acquire.gpu.u32 %0, [%1];" : "=r"(v) : "l"(p) : "memory");
    return v;
}
__device__ __forceinline__ void st_rel(unsigned* p, unsigned v) {
    asm volatile("st.release.gpu.u32 [%0], %1;" :: "l"(p), "r"(v) : "memory");
}
__device__ __forceinline__ void fma2(ull &d, ull a, ull b) {
    asm("fma.rn.f32x2 %0, %1, %2, %0;" : "+l"(d) : "l"(a), "l"(b));
}
__device__ __forceinline__ void unpack2(ull v, float &lo, float &hi) {
    asm("mov.b64 {%0, %1}, %2;" : "=f"(lo), "=f"(hi) : "l"(v));
}

// ---------------- projection GEMM: C[M,512] = A[M,K] @ W[512,K]^T + bias ----
// 64x64 tile, BK=8, 256 threads, 4x4 micro-tile (R3 config: 426us, occ 59%).
__global__ void __launch_bounds__(256) gemm512(
    const float* __restrict__ Aext, int a_is_h1,
    const float* __restrict__ W, const float* __restrict__ bias,
    int out_sel, int K)
{
    const float* A = a_is_h1 ? g_h1 : Aext;
    float* C = (out_sel == 0) ? g_wh0 : (out_sel == 1) ? g_wz0
             : (out_sel == 2) ? g_wh1 : g_wz1;

    __shared__ __align__(16) float As[8][64];
    __shared__ __align__(16) float Bs[8][64];

    int tid = threadIdx.x;
    int m0 = blockIdx.x * 64, n0 = blockIdx.y * 64;
    int lr = tid >> 2;            // 0..63
    int lk = (tid & 3) * 2;       // 0,2,4,6
    const float* ap = A + (size_t)(m0 + lr) * K + lk;
    const float* wp = W + (size_t)(n0 + lr) * K + lk;
    int ty = tid >> 4, tx = tid & 15;

    float acc[4][4] = {};
    int nkb = K / 8;
    for (int kb = 0; kb < nkb; ++kb) {
        float2 av = *(const float2*)ap;
        float2 wv = *(const float2*)wp;
        ap += 8; wp += 8;
        As[lk][lr] = av.x; As[lk+1][lr] = av.y;
        Bs[lk][lr] = wv.x; Bs[lk+1][lr] = wv.y;
        __syncthreads();
        #pragma unroll
        for (int k = 0; k < 8; ++k) {
            float4 a4 = *(const float4*)&As[k][ty*4];
            float4 b4 = *(const float4*)&Bs[k][tx*4];
            float a_[4] = {a4.x, a4.y, a4.z, a4.w};
            float b_[4] = {b4.x, b4.y, b4.z, b4.w};
            #pragma unroll
            for (int i = 0; i < 4; ++i)
                #pragma unroll
                for (int j = 0; j < 4; ++j)
                    acc[i][j] += a_[i] * b_[j];
        }
        __syncthreads();
    }
    #pragma unroll
    for (int i = 0; i < 4; ++i) {
        float4 o;
        o.x = acc[i][0] + bias[n0 + tx*4 + 0];
        o.y = acc[i][1] + bias[n0 + tx*4 + 1];
        o.z = acc[i][2] + bias[n0 + tx*4 + 2];
        o.w = acc[i][3] + bias[n0 + tx*4 + 3];
        *(float4*)&C[(size_t)(m0 + ty*4 + i) * HH + n0 + tx*4] = o;
    }
}

// ---------------- persistent recurrence kernel ------------------------------
// 128 CTAs x 256 threads. CTA owns 4 output columns (both gates).
// warp w: bg = w>>1 (batch group of 4), rg = w&1 (0: z/Uz, 1: hcand/Uh).
// lane covers k-pairs k0 = lane*2 + 64*i, i<8; U slice in registers (f32x2).
// Barrier: per-CTA release slots -> CTA0 aggregates in parallel -> g_gen flag.
__global__ void __launch_bounds__(256, 1) recur(
    const float* __restrict__ Uh, const float* __restrict__ Uz,
    int layer, float* __restrict__ out_ext)
{
    const float* wh = layer ? g_wh1 : g_wh0;
    const float* wz = layer ? g_wz1 : g_wz0;
    float* out = out_ext ? out_ext : g_h1;

    __shared__ __align__(16) float hs[BB][HH];   // 32 KB
    __shared__ float sdot[2][BB][4];
    __shared__ unsigned s_base;

    int tid  = threadIdx.x;
    int w    = tid >> 5, lane = tid & 31;
    int bg   = w >> 1,   rg   = w & 1;
    int bid  = blockIdx.x;
    int j0   = bid * 4;

    if (tid == 0) s_base = ld_acq(&g_gen);

    // U slice into registers: 4 rows x 8 k-pairs (f32x2)
    const float* U = rg ? Uh : Uz;
    ull Ureg[4][8];
    int k0 = lane * 2;
    #pragma unroll
    for (int r = 0; r < 4; ++r)
        #pragma unroll
        for (int i = 0; i < 8; ++i)
            Ureg[r][i] = *(const ull*)&U[(size_t)(j0 + r) * HH + k0 + 64*i];

    // h0 = 0
    for (int f = tid; f < BB*HH/4; f += 256)
        ((float4*)hs)[f] = make_float4(0.f, 0.f, 0.f, 0.f);
    __syncthreads();
    unsigned base = s_base;

    // per-thread gate assignment (threads 0..63)
    int gb = tid >> 2, gr = tid & 3;
    float wzv = 0.f, whv = 0.f;
    int obase = (0 * BB + gb) * HH + j0 + gr;
    if (tid < 64) {
        wzv = __ldcg(&wz[obase]);
        whv = __ldcg(&wh[obase]);
    }

    for (int t = 0; t < TT; ++t) {
        unsigned tgt = base + (unsigned)t;
        if (t > 0) {
            // wait for generation base+t (h_{t-1} published)
            if (bid == 0) {
                if (tid < NC) {
                    while ((int)(ld_acq(&g_slots[tid]) - tgt) < 0) { }
                }
                __syncthreads();
                if (tid == 0) st_rel(&g_gen, tgt);
            } else {
                if (tid == 0) {
                    while ((int)(ld_acq(&g_gen) - tgt) < 0) { }
                }
                __syncthreads();
            }
            const float4* src = (const float4*)(g_hbuf + (size_t)((t+1)&1) * BB * HH);
            #pragma unroll
            for (int q = 0; q < 8; ++q) {
                int f = tid + q * 256;
                ((float4*)hs)[f] = __ldcg(src + f);
            }
            __syncthreads();
        }

        // dot products: acc2[r][b'] over this lane's k-pairs (packed f32x2)
        ull acc2[4][4];
        #pragma unroll
        for (int r = 0; r < 4; ++r)
            #pragma unroll
            for (int b = 0; b < 4; ++b) acc2[r][b] = 0ull;

        const float* hb = &hs[bg * 4][0];
        #pragma unroll
        for (int i = 0; i < 8; ++i) {
            int k = k0 + 64 * i;
            ull h0v = *(const ull*)&hb[k];
            ull h1v = *(const ull*)&hb[HH + k];
            ull h2v = *(const ull*)&hb[2*HH + k];
            ull h3v = *(const ull*)&hb[3*HH + k];
            #pragma unroll
            for (int r = 0; r < 4; ++r) {
                fma2(acc2[r][0], Ureg[r][i], h0v);
                fma2(acc2[r][1], Ureg[r][i], h1v);
                fma2(acc2[r][2], Ureg[r][i], h2v);
                fma2(acc2[r][3], Ureg[r][i], h3v);
            }
        }
        float acc[4][4];
        #pragma unroll
        for (int r = 0; r < 4; ++r)
            #pragma unroll
            for (int b = 0; b < 4; ++b) {
                float lo, hi; unpack2(acc2[r][b], lo, hi);
                acc[r][b] = lo + hi;
            }
        // butterfly reduce over 32 lanes
        #pragma unroll
        for (int m = 16; m >= 1; m >>= 1)
            #pragma unroll
            for (int r = 0; r < 4; ++r)
                #pragma unroll
                for (int b = 0; b < 4; ++b)
                    acc[r][b] += __shfl_xor_sync(0xffffffffu, acc[r][b], m);
        if (lane < 16)
            sdot[rg][bg * 4 + (lane & 3)][lane >> 2] = acc[lane >> 2][lane & 3];
        __syncthreads();

        if (tid < 64) {
            float z  = 1.f / (1.f + __expf(-(wzv + sdot[0][gb][gr])));
            float hc = whv + sdot[1][gb][gr];
            hc = hc > 0.f ? hc : 0.f;
            float hn = z * hs[gb][j0 + gr] + (1.f - z) * hc;
            g_hbuf[(size_t)(t & 1) * BB * HH + gb * HH + j0 + gr] = hn;
            out[obase] = hn;
            // prefetch next step's projections (overlaps barrier wait)
            if (t + 1 < TT) {
                obase += BB * HH;
                wzv = __ldcg(&wz[obase]);
                whv = __ldcg(&wh[obase]);
            }
        }
        __syncthreads();

        // arrive: per-CTA slot release (parallel, no atomic serialization)
        if (tid == 0) {
            __threadfence();
            st_rel(&g_slots[bid], tgt + 1u);
        }
    }
    // leave g_gen consistent with slots for the next launch:
    // CTA0 publishes the final generation.
    if (bid == 0) {
        unsigned tgt = base + (unsigned)TT;
        if (tid < NC) {
            while ((int)(ld_acq(&g_slots[tid]) - tgt) < 0) { }
        }
        __syncthreads();
        if (tid == 0) st_rel(&g_gen, tgt);
    }
}

// ---------------- launch ----------------------------------------------------
extern "C" void kernel_launch(void* const* d_in, const int* in_sizes, int n_in,
                              void* d_out, int out_size) {
    const float* x   = (const float*)d_in[0];
    const float* Wh0 = (const float*)d_in[1];
    const float* bh0 = (const float*)d_in[2];
    const float* Wz0 = (const float*)d_in[3];
    const float* bz0 = (const float*)d_in[4];
    const float* Uh0 = (const float*)d_in[5];
    const float* Uz0 = (const float*)d_in[6];
    const float* Wh1 = (const float*)d_in[7];
    const float* bh1 = (const float*)d_in[8];
    const float* Wz1 = (const float*)d_in[9];
    const float* bz1 = (const float*)d_in[10];
    const float* Uh1 = (const float*)d_in[11];
    const float* Uz1 = (const float*)d_in[12];
    float* out = (float*)d_out;

    dim3 gg(MM / 64, HH / 64);
    gemm512<<<gg, 256>>>(x, 0, Wh0, bh0, 0, FF);
    gemm512<<<gg, 256>>>(x, 0, Wz0, bz0, 1, FF);
    recur<<<NC, 256>>>(Uh0, Uz0, 0, nullptr);
    gemm512<<<gg, 256>>>(nullptr, 1, Wh1, bh1, 2, HH);
    gemm512<<<gg, 256>>>(nullptr, 1, Wz1, bz1, 3, HH);
    recur<<<NC, 256>>>(Uh1, Uz1, 1, out);
}

// round 13
// speedup vs baseline: 2.3211x; 2.3211x over previous
#include <cuda_runtime.h>
#include <math.h>

#define TT 1500
#define BB 16
#define FF 440
#define HH 512
#define MM (TT*BB)      // 24000
#define NC 128          // persistent CTAs (single wave)

typedef unsigned long long ull;

// ---------------- device scratch (no allocations allowed) -------------------
__device__ float g_wh0[MM*HH];
__device__ float g_wz0[MM*HH];
__device__ float g_h1buf[2*BB*HH];
__device__ float g_h2buf[2*BB*HH];
__device__ unsigned g_count;   // zero-init; monotonic arrivals
__device__ unsigned g_gen;     // zero-init; completed generations

// ---------------- helpers ----------------------------------------------------
__device__ __forceinline__ unsigned ld_acq(const unsigned* p) {
    unsigned v;
    asm volatile("ld.acquire.gpu.u32 %0, [%1];" : "=r"(v) : "l"(p) : "memory");
    return v;
}
__device__ __forceinline__ void st_rel(unsigned* p, unsigned v) {
    asm volatile("st.release.gpu.u32 [%0], %1;" :: "l"(p), "r"(v) : "memory");
}
__device__ __forceinline__ void fma2(ull &d, ull a, ull b) {
    asm("fma.rn.f32x2 %0, %1, %2, %0;" : "+l"(d) : "l"(a), "l"(b));
}
__device__ __forceinline__ void unpack2(ull v, float &lo, float &hi) {
    asm("mov.b64 {%0, %1}, %2;" : "=f"(lo), "=f"(hi) : "l"(v));
}

// fold-reduce 16 values over 32 lanes: returns full sum of val[(lane>>1)&15]
__device__ __forceinline__ float warp_fold16(const float v16[16], int lane) {
    float v8[8];
    {
        bool hi = (lane & 16) != 0;
        #pragma unroll
        for (int i = 0; i < 8; ++i) {
            float send = hi ? v16[i] : v16[i+8];
            float keep = hi ? v16[i+8] : v16[i];
            v8[i] = keep + __shfl_xor_sync(0xffffffffu, send, 16);
        }
    }
    float v4[4];
    {
        bool hi = (lane & 8) != 0;
        #pragma unroll
        for (int i = 0; i < 4; ++i) {
            float send = hi ? v4[0]*0.f + (hi ? v8[i] : v8[i+4]) : v8[i+4];
            // (no-op guard removed below for clarity)
            float s2 = hi ? v8[i] : v8[i+4];
            float keep = hi ? v8[i+4] : v8[i];
            v4[i] = keep + __shfl_xor_sync(0xffffffffu, s2, 8);
            (void)send;
        }
    }
    float v2[2];
    {
        bool hi = (lane & 4) != 0;
        #pragma unroll
        for (int i = 0; i < 2; ++i) {
            float send = hi ? v4[i] : v4[i+2];
            float keep = hi ? v4[i+2] : v4[i];
            v2[i] = keep + __shfl_xor_sync(0xffffffffu, send, 4);
        }
    }
    float v1;
    {
        bool hi = (lane & 2) != 0;
        float send = hi ? v2[0] : v2[1];
        float keep = hi ? v2[1] : v2[0];
        v1 = keep + __shfl_xor_sync(0xffffffffu, send, 2);
    }
    v1 += __shfl_xor_sync(0xffffffffu, v1, 1);
    return v1;
}

// dot block: weights from registers
__device__ __forceinline__ void dots_reg(const ull Ur[4][8], const float* hb,
                                         int k0, float val[16]) {
    ull acc2[16];
    #pragma unroll
    for (int j = 0; j < 16; ++j) acc2[j] = 0ull;
    #pragma unroll
    for (int i = 0; i < 8; ++i) {
        int k = k0 + 64*i;
        ull h0 = *(const ull*)&hb[k];
        ull h1 = *(const ull*)&hb[HH + k];
        ull h2 = *(const ull*)&hb[2*HH + k];
        ull h3 = *(const ull*)&hb[3*HH + k];
        #pragma unroll
        for (int r = 0; r < 4; ++r) {
            fma2(acc2[r*4+0], Ur[r][i], h0);
            fma2(acc2[r*4+1], Ur[r][i], h1);
            fma2(acc2[r*4+2], Ur[r][i], h2);
            fma2(acc2[r*4+3], Ur[r][i], h3);
        }
    }
    #pragma unroll
    for (int j = 0; j < 16; ++j) {
        float lo, hi; unpack2(acc2[j], lo, hi);
        val[j] = lo + hi;
    }
}

// dot block: weights from shared memory (4 rows, stride HH)
__device__ __forceinline__ void dots_smem(const float* wbase, const float* hb,
                                          int k0, float val[16]) {
    ull acc2[16];
    #pragma unroll
    for (int j = 0; j < 16; ++j) acc2[j] = 0ull;
    #pragma unroll
    for (int i = 0; i < 8; ++i) {
        int k = k0 + 64*i;
        ull h0 = *(const ull*)&hb[k];
        ull h1 = *(const ull*)&hb[HH + k];
        ull h2 = *(const ull*)&hb[2*HH + k];
        ull h3 = *(const ull*)&hb[3*HH + k];
        #pragma unroll
        for (int r = 0; r < 4; ++r) {
            ull wv = *(const ull*)&wbase[r*HH + k];
            fma2(acc2[r*4+0], wv, h0);
            fma2(acc2[r*4+1], wv, h1);
            fma2(acc2[r*4+2], wv, h2);
            fma2(acc2[r*4+3], wv, h3);
        }
    }
    #pragma unroll
    for (int j = 0; j < 16; ++j) {
        float lo, hi; unpack2(acc2[j], lo, hi);
        val[j] = lo + hi;
    }
}

// ---------------- projection GEMM: C[M,512] = A[M,K] @ W[512,K]^T + bias ----
__global__ void __launch_bounds__(256) gemm512(
    const float* __restrict__ A,
    const float* __restrict__ W, const float* __restrict__ bias,
    int out_sel, int K)
{
    float* C = out_sel ? g_wz0 : g_wh0;

    __shared__ __align__(16) float As[8][64];
    __shared__ __align__(16) float Bs[8][64];

    int tid = threadIdx.x;
    int m0 = blockIdx.x * 64, n0 = blockIdx.y * 64;
    int lr = tid >> 2;
    int lk = (tid & 3) * 2;
    const float* ap = A + (size_t)(m0 + lr) * K + lk;
    const float* wp = W + (size_t)(n0 + lr) * K + lk;
    int ty = tid >> 4, tx = tid & 15;

    float acc[4][4] = {};
    int nkb = K / 8;
    for (int kb = 0; kb < nkb; ++kb) {
        float2 av = *(const float2*)ap;
        float2 wv = *(const float2*)wp;
        ap += 8; wp += 8;
        As[lk][lr] = av.x; As[lk+1][lr] = av.y;
        Bs[lk][lr] = wv.x; Bs[lk+1][lr] = wv.y;
        __syncthreads();
        #pragma unroll
        for (int k = 0; k < 8; ++k) {
            float4 a4 = *(const float4*)&As[k][ty*4];
            float4 b4 = *(const float4*)&Bs[k][tx*4];
            float a_[4] = {a4.x, a4.y, a4.z, a4.w};
            float b_[4] = {b4.x, b4.y, b4.z, b4.w};
            #pragma unroll
            for (int i = 0; i < 4; ++i)
                #pragma unroll
                for (int j = 0; j < 4; ++j)
                    acc[i][j] += a_[i] * b_[j];
        }
        __syncthreads();
    }
    #pragma unroll
    for (int i = 0; i < 4; ++i) {
        float4 o;
        o.x = acc[i][0] + bias[n0 + tx*4 + 0];
        o.y = acc[i][1] + bias[n0 + tx*4 + 1];
        o.z = acc[i][2] + bias[n0 + tx*4 + 2];
        o.w = acc[i][3] + bias[n0 + tx*4 + 3];
        *(float4*)&C[(size_t)(m0 + ty*4 + i) * HH + n0 + tx*4] = o;
    }
}

// ---------------- fused persistent 2-layer kernel ----------------------------
// iter t: layer1 step t (h1[t] from h1[t-1]) AND layer2 step t-1
// (h2[t-1] from h2[t-2], with projections of h1[t-1] computed in-kernel).
// 128 CTAs x 256 thr; CTA owns 4 columns j0..j0+3 of both layers.
// warp w: bg=w>>1 (4 batches), rg=w&1 (0=z gate, 1=h gate).
__global__ void __launch_bounds__(256, 1) fused(
    const float* __restrict__ Uh0, const float* __restrict__ Uz0,
    const float* __restrict__ Uh1, const float* __restrict__ Uz1,
    const float* __restrict__ Wh1, const float* __restrict__ Wz1,
    const float* __restrict__ bh1, const float* __restrict__ bz1,
    float* __restrict__ out)
{
    extern __shared__ float sm[];
    float* h1s = sm;                 // 8192 f : h1[t-1]
    float* h2s = sm + 8192;          // 8192 f : h2[t-2]
    float* w1s = sm + 16384;         // 4096 f : Wz1/Wh1 rows j0..j0+3
    float* u1s = sm + 20480;         // 4096 f : Uz1/Uh1 rows j0..j0+3
    float* sdA = sm + 24576;         // 128 f  : layer1 dots [gate][b][r]
    float* sdP = sm + 24704;         // 128 f  : layer2 proj dots
    float* sdQ = sm + 24832;         // 128 f  : layer2 recur dots
    __shared__ unsigned s_base;

    int tid = threadIdx.x, w = tid >> 5, lane = tid & 31;
    int bg = w >> 1, rg = w & 1;
    int j0 = blockIdx.x * 4;
    int k0 = lane * 2;

    if (tid == 0) s_base = ld_acq(&g_gen);

    // layer-1 U slice in registers
    const float* U0 = rg ? Uh0 : Uz0;
    ull U0r[4][8];
    #pragma unroll
    for (int r = 0; r < 4; ++r)
        #pragma unroll
        for (int i = 0; i < 8; ++i)
            U0r[r][i] = *(const ull*)&U0[(size_t)(j0 + r) * HH + k0 + 64*i];

    // layer-2 weight slices into smem (persistent)
    for (int q = tid; q < 1024; q += 256) {
        int g = q >> 9, r = (q >> 7) & 3, kk = (q & 127) * 4;
        const float* Wp = g ? Wh1 : Wz1;
        const float* Up = g ? Uh1 : Uz1;
        ((float4*)w1s)[q] = *(const float4*)&Wp[(size_t)(j0 + r) * HH + kk];
        ((float4*)u1s)[q] = *(const float4*)&Up[(size_t)(j0 + r) * HH + kk];
    }
    __syncthreads();
    unsigned base = s_base;

    int gb = tid >> 2, gr = tid & 3;
    float wzv = 0.f, whv = 0.f, bh1v = 0.f, bz1v = 0.f;
    int obase = gb * HH + j0 + gr;
    if (tid < 64) {
        wzv = __ldcg(&g_wz0[obase]);
        whv = __ldcg(&g_wh0[obase]);
        bz1v = bz1[j0 + gr];
        bh1v = bh1[j0 + gr];
    }

    for (int t = 0; t <= TT; ++t) {
        if (t > 0) {
            unsigned tgt = base + (unsigned)t;
            if (tid == 0) {
                while ((int)(ld_acq(&g_gen) - tgt) < 0) { }
            }
            __syncthreads();
        }
        // stage h1[t-1], h2[t-2]
        if (t == 0) {
            for (int f = tid; f < 2048; f += 256)
                ((float4*)h1s)[f] = make_float4(0.f,0.f,0.f,0.f);
        } else {
            const float4* s1 = (const float4*)(g_h1buf + (size_t)((t-1)&1) * BB * HH);
            #pragma unroll
            for (int q = 0; q < 8; ++q)
                ((float4*)h1s)[tid + q*256] = __ldcg(s1 + tid + q*256);
        }
        if (t <= 1) {
            for (int f = tid; f < 2048; f += 256)
                ((float4*)h2s)[f] = make_float4(0.f,0.f,0.f,0.f);
        } else {
            const float4* s2 = (const float4*)(g_h2buf + (size_t)(t&1) * BB * HH);
            #pragma unroll
            for (int q = 0; q < 8; ++q)
                ((float4*)h2s)[tid + q*256] = __ldcg(s2 + tid + q*256);
        }
        __syncthreads();

        const float* hb1 = h1s + bg * 4 * HH;
        const float* hb2 = h2s + bg * 4 * HH;

        // ---- layer 1, step t ----
        if (t < TT) {
            float val[16];
            dots_reg(U0r, hb1, k0, val);
            float v1 = warp_fold16(val, lane);
            int v = (lane >> 1) & 15;
            if (!(lane & 1))
                sdA[rg*64 + (bg*4 + (v&3))*4 + (v>>2)] = v1;
            __syncthreads();
            if (tid < 64) {
                float z  = 1.f / (1.f + __expf(-(wzv + sdA[gb*4 + gr])));
                float hc = whv + sdA[64 + gb*4 + gr];
                hc = hc > 0.f ? hc : 0.f;
                float h1n = z * h1s[gb*HH + j0 + gr] + (1.f - z) * hc;
                g_h1buf[(size_t)(t&1) * BB * HH + gb*HH + j0 + gr] = h1n;
            }
        }
        // ---- layer 2, step t-1 ----
        if (t >= 1) {
            {
                float val[16];
                dots_smem(w1s + rg*2048, hb1, k0, val);   // proj of h1[t-1]
                float v1 = warp_fold16(val, lane);
                int v = (lane >> 1) & 15;
                if (!(lane & 1))
                    sdP[rg*64 + (bg*4 + (v&3))*4 + (v>>2)] = v1;
            }
            {
                float val[16];
                dots_smem(u1s + rg*2048, hb2, k0, val);   // recur over h2[t-2]
                float v1 = warp_fold16(val, lane);
                int v = (lane >> 1) & 15;
                if (!(lane & 1))
                    sdQ[rg*64 + (bg*4 + (v&3))*4 + (v>>2)] = v1;
            }
            __syncthreads();
            if (tid < 64) {
                float zp  = 1.f / (1.f + __expf(-(bz1v + sdP[gb*4 + gr] + sdQ[gb*4 + gr])));
                float hcp = bh1v + sdP[64 + gb*4 + gr] + sdQ[64 + gb*4 + gr];
                hcp = hcp > 0.f ? hcp : 0.f;
                float h2n = zp * h2s[gb*HH + j0 + gr] + (1.f - zp) * hcp;
                g_h2buf[(size_t)((t-1)&1) * BB * HH + gb*HH + j0 + gr] = h2n;
                out[(size_t)((t-1)*BB + gb) * HH + j0 + gr] = h2n;
            }
        }
        // prefetch next step's layer-1 projections (overlaps barrier)
        if (tid < 64 && t + 1 < TT) {
            obase += BB * HH;
            wzv = __ldcg(&g_wz0[obase]);
            whv = __ldcg(&g_wh0[obase]);
        }
        __syncthreads();

        // arrive (iters 0..TT-1): atomic counter, last publishes generation
        if (t < TT && tid == 0) {
            __threadfence();
            unsigned old = atomicAdd(&g_count, 1u);
            if (old + 1u == (base + (unsigned)t + 1u) * NC)
                st_rel(&g_gen, base + (unsigned)t + 1u);
        }
    }
}

// ---------------- launch ----------------------------------------------------
#define FUSED_SMEM ((24960) * 4)

extern "C" void kernel_launch(void* const* d_in, const int* in_sizes, int n_in,
                              void* d_out, int out_size) {
    const float* x   = (const float*)d_in[0];
    const float* Wh0 = (const float*)d_in[1];
    const float* bh0 = (const float*)d_in[2];
    const float* Wz0 = (const float*)d_in[3];
    const float* bz0 = (const float*)d_in[4];
    const float* Uh0 = (const float*)d_in[5];
    const float* Uz0 = (const float*)d_in[6];
    const float* Wh1 = (const float*)d_in[7];
    const float* bh1 = (const float*)d_in[8];
    const float* Wz1 = (const float*)d_in[9];
    const float* bz1 = (const float*)d_in[10];
    const float* Uh1 = (const float*)d_in[11];
    const float* Uz1 = (const float*)d_in[12];
    float* out = (float*)d_out;

    cudaFuncSetAttribute(fused, cudaFuncAttributeMaxDynamicSharedMemorySize,
                         FUSED_SMEM);

    dim3 gg(MM / 64, HH / 64);
    gemm512<<<gg, 256>>>(x, Wh0, bh0, 0, FF);
    gemm512<<<gg, 256>>>(x, Wz0, bz0, 1, FF);
    fused<<<NC, 256, FUSED_SMEM>>>(Uh0, Uz0, Uh1, Uz1, Wh1, Wz1, bh1, bz1, out);
}